// round 10
// baseline (speedup 1.0000x reference)
#include <cuda_runtime.h>

#define PI_F 3.14159265358979323846f

// scratch: pre-activations pre[B][4], circuit unitary U[16][16] complex
__device__ float  g_pre[65536 * 4];
__device__ float2 g_U[256];          // g_U[j*16+k] = U[j][k] (amp j, column k)

// ---------------------------------------------------------------------------
// fold: butterfly step that merges two accumulators while halving lane span.
// ---------------------------------------------------------------------------
__device__ __forceinline__ float foldf(float a, float b, int m, int lane) {
    const float s = (lane & m) ? a : b;
    const float r = __shfl_xor_sync(0xffffffffu, s, m);
    return (((lane & m) ? b : a) + r);
}

__device__ __forceinline__ float dot4acc(const float4 a, const float4 b,
                                         float acc) {
    return fmaf(a.x, b.x, fmaf(a.y, b.y, fmaf(a.z, b.z,
           fmaf(a.w, b.w, acc))));
}

// ---------------------------------------------------------------------------
// K1: GEMV pre = x @ W_pre^T (W in smem -> ~64 regs -> 3 blocks/SM),
//     PLUS one extra block (the last one) that builds the 16x16 circuit
//     unitary U and writes it to g_U (overlapped with the GEMV wave).
// ---------------------------------------------------------------------------
__global__ __launch_bounds__(256, 3) void gemv_kernel(
    const float4* __restrict__ x4,      // [B,128] float4
    const float4* __restrict__ Wpre4,   // [4,128] float4
    const float* __restrict__ q_weights,// [6,4,3]
    int B)
{
    const int tid  = threadIdx.x;
    const int lane = tid & 31;

    if (blockIdx.x == gridDim.x - 1) {
        // ================= U-builder block =================
        __shared__ float4 g_sh[24][2];     // gate coefficients
        __shared__ float2 S[16][16];       // [column][amplitude]
        __shared__ float2 T[16][16];

        if (tid < 24) {
            const float phi = q_weights[tid * 3 + 0];
            const float th  = q_weights[tid * 3 + 1];
            const float om  = q_weights[tid * 3 + 2];
            float c, s, cp, sp, cm, sm;
            sincosf(0.5f * th, &s, &c);
            sincosf(0.5f * (phi + om), &sp, &cp);
            sincosf(0.5f * (phi - om), &sm, &cm);
            g_sh[tid][0] = make_float4(cp * c, -sp * c, -cm * s, -sm * s);
            g_sh[tid][1] = make_float4(cm * s, -sm * s,  cp * c,  sp * c);
        }
        if (tid < 128) {
            const int c = tid >> 3;
            const int m = tid & 7;
            S[c][m]     = make_float2((m == c)     ? 1.f : 0.f, 0.f);
            S[c][m + 8] = make_float2((m + 8 == c) ? 1.f : 0.f, 0.f);
        }
        __syncthreads();

        if (tid < 128) {
            const int c = tid >> 3;
            const int m = tid & 7;
#pragma unroll 1
            for (int l = 0; l < 6; ++l) {
                // 4 Rot gates
#pragma unroll
                for (int w = 0; w < 4; ++w) {
                    const int ST = 8 >> w;
                    const int i0 = ((m & ~(ST - 1)) << 1) | (m & (ST - 1));
                    const int i1 = i0 + ST;
                    const float4 g0 = g_sh[l * 4 + w][0];
                    const float4 g1 = g_sh[l * 4 + w][1];
                    const float2 a = S[c][i0];
                    const float2 b = S[c][i1];
                    S[c][i0] = make_float2(
                        g0.x * a.x - g0.y * a.y + g0.z * b.x - g0.w * b.y,
                        g0.x * a.y + g0.y * a.x + g0.z * b.y + g0.w * b.x);
                    S[c][i1] = make_float2(
                        g1.x * a.x - g1.y * a.y + g1.z * b.x - g1.w * b.y,
                        g1.x * a.y + g1.y * a.x + g1.z * b.y + g1.w * b.x);
                    __syncthreads();
                }
                // CNOT ring (w, (w+R)%4) as one index permutation
                const int R = l % 3 + 1;
#pragma unroll
                for (int half = 0; half < 2; ++half) {
                    const int i = m + half * 8;
                    int j = i;
#pragma unroll
                    for (int w = 0; w < 4; ++w)
                        if (j & (8 >> w)) j ^= (8 >> ((w + R) & 3));
                    T[c][j] = S[c][i];
                }
                __syncthreads();
                S[c][m]     = T[c][m];
                S[c][m + 8] = T[c][m + 8];
                __syncthreads();
            }
            // write U: column c's amplitude j = U[j][c]
            g_U[m * 16 + c]       = S[c][m];
            g_U[(m + 8) * 16 + c] = S[c][m + 8];
        }
        return;
    }

    // ================= GEMV blocks =================
    __shared__ float4 Ws[4 * 128];      // W_pre, [q][col4]
#pragma unroll
    for (int i = 0; i < 2; ++i)
        Ws[i * 256 + tid] = Wpre4[i * 256 + tid];
    __syncthreads();

    const int gwarp   = (blockIdx.x * 256 + tid) >> 5;
    const int rowBase = gwarp * 8;

#pragma unroll 1
    for (int pi = 0; pi < 4; ++pi) {
        int r0 = rowBase + pi * 2;
        int r1 = r0 + 1;
        if (r0 >= B) r0 = B - 1;
        if (r1 >= B) r1 = B - 1;

        // 8 independent coalesced LDG.128
        float4 xv0[4], xv1[4];
#pragma unroll
        for (int it = 0; it < 4; ++it)
            xv0[it] = x4[(long)r0 * 128 + it * 32 + lane];
#pragma unroll
        for (int it = 0; it < 4; ++it)
            xv1[it] = x4[(long)r1 * 128 + it * 32 + lane];

        float a0 = 0.f, a1 = 0.f, a2 = 0.f, a3 = 0.f;
        float b0 = 0.f, b1 = 0.f, b2 = 0.f, b3 = 0.f;
#pragma unroll
        for (int it = 0; it < 4; ++it) {
            const float4 w0 = Ws[0 * 128 + it * 32 + lane];
            const float4 w1 = Ws[1 * 128 + it * 32 + lane];
            const float4 w2 = Ws[2 * 128 + it * 32 + lane];
            const float4 w3 = Ws[3 * 128 + it * 32 + lane];
            a0 = dot4acc(xv0[it], w0, a0);
            a1 = dot4acc(xv0[it], w1, a1);
            a2 = dot4acc(xv0[it], w2, a2);
            a3 = dot4acc(xv0[it], w3, a3);
            b0 = dot4acc(xv1[it], w0, b0);
            b1 = dot4acc(xv1[it], w1, b1);
            b2 = dot4acc(xv1[it], w2, b2);
            b3 = dot4acc(xv1[it], w3, b3);
        }

        // packed reduction: 9 shuffles for 8 accumulators.
        // lane bit4 selects row (a/b), lane bits [3:2] select qubit.
        const float t0 = foldf(a0, b0, 16, lane);
        const float t1 = foldf(a1, b1, 16, lane);
        const float t2 = foldf(a2, b2, 16, lane);
        const float t3 = foldf(a3, b3, 16, lane);
        const float u0 = foldf(t0, t2, 8, lane);
        const float u1 = foldf(t1, t3, 8, lane);
        float v = foldf(u0, u1, 4, lane);
        v += __shfl_xor_sync(0xffffffffu, v, 2);
        v += __shfl_xor_sync(0xffffffffu, v, 1);

        if ((lane & 3) == 0) {
            const int rsel = lane >> 4;
            const int q = (lane >> 2) & 3;
            g_pre[(long)(rsel ? r1 : r0) * 4 + q] = v;
        }
    }
}

// ---------------------------------------------------------------------------
// K2: y = U * s0 per row, then probs -> Z expectations -> post linear.
// ~700 instrs/row instead of ~3300 (circuit collapsed into U).
// ---------------------------------------------------------------------------
__global__ __launch_bounds__(256) void circuit_kernel(
    const float* __restrict__ b_pre,    // [4]
    const float* __restrict__ W_post,   // [10,4]
    const float* __restrict__ b_post,   // [10]
    float* __restrict__ out,            // [B,10]
    int B)
{
    __shared__ float2 Us[256];          // U[j][k], row-major
    __shared__ float  wpost_sh[40];
    __shared__ float  bpost_sh[10];

    const int tid = threadIdx.x;
    if (tid < 128)
        reinterpret_cast<float4*>(Us)[tid] =
            reinterpret_cast<const float4*>(g_U)[tid];
    else if (tid < 168)      wpost_sh[tid - 128] = W_post[tid - 128];
    else if (tid < 178)      bpost_sh[tid - 168] = b_post[tid - 168];
    __syncthreads();

    const long row = (long)blockIdx.x * 256 + tid;
    if (row >= B) return;

    const float4 p = *reinterpret_cast<const float4*>(g_pre + row * 4);

    float cw[4], sw[4];
    {
        float ang;
        ang = tanhf(p.x + __ldg(b_pre + 0)) * PI_F;
        __sincosf(0.5f * ang, &sw[0], &cw[0]);
        ang = tanhf(p.y + __ldg(b_pre + 1)) * PI_F;
        __sincosf(0.5f * ang, &sw[1], &cw[1]);
        ang = tanhf(p.z + __ldg(b_pre + 2)) * PI_F;
        __sincosf(0.5f * ang, &sw[2], &cw[2]);
        ang = tanhf(p.w + __ldg(b_pre + 3)) * PI_F;
        __sincosf(0.5f * ang, &sw[3], &cw[3]);
    }

    // real product state after the RY layer
    float s0[16];
#pragma unroll
    for (int i = 0; i < 16; ++i)
        s0[i] = ((i & 8) ? sw[0] : cw[0]) * ((i & 4) ? sw[1] : cw[1]) *
                ((i & 2) ? sw[2] : cw[2]) * ((i & 1) ? sw[3] : cw[3]);

    // y = U s0 (s0 real); accumulate Z expectations from |y_j|^2
    float e0 = 0.f, e1 = 0.f, e2 = 0.f, e3 = 0.f;
#pragma unroll
    for (int j = 0; j < 16; ++j) {
        const float4* Uj = reinterpret_cast<const float4*>(&Us[j * 16]);
        float yr = 0.f, yi = 0.f;
#pragma unroll
        for (int kk = 0; kk < 8; ++kk) {
            const float4 v = Uj[kk];            // (re_k, im_k, re_k+1, im_k+1)
            const float sa = s0[2 * kk];
            const float sb = s0[2 * kk + 1];
            yr = fmaf(v.x, sa, fmaf(v.z, sb, yr));
            yi = fmaf(v.y, sa, fmaf(v.w, sb, yi));
        }
        const float pr = fmaf(yr, yr, yi * yi);
        e0 += (j & 8) ? -pr : pr;
        e1 += (j & 4) ? -pr : pr;
        e2 += (j & 2) ? -pr : pr;
        e3 += (j & 1) ? -pr : pr;
    }

    float o[10];
#pragma unroll
    for (int c = 0; c < 10; ++c) {
        o[c] = bpost_sh[c]
             + e0 * wpost_sh[c * 4 + 0] + e1 * wpost_sh[c * 4 + 1]
             + e2 * wpost_sh[c * 4 + 2] + e3 * wpost_sh[c * 4 + 3];
    }
    float2* op = reinterpret_cast<float2*>(out + row * 10);
#pragma unroll
    for (int c = 0; c < 5; ++c) op[c] = make_float2(o[2 * c], o[2 * c + 1]);
}

extern "C" void kernel_launch(void* const* d_in, const int* in_sizes, int n_in,
                              void* d_out, int out_size) {
    const float* x    = (const float*)d_in[0];
    const float* Wpre = (const float*)d_in[1];
    const float* bpre = (const float*)d_in[2];
    const float* qw   = (const float*)d_in[3];
    const float* Wpo  = (const float*)d_in[4];
    const float* bpo  = (const float*)d_in[5];
    float* out = (float*)d_out;

    const int B = in_sizes[0] / 512;

    // K1: 64 rows per block + 1 extra block that builds U (overlapped)
    const int grid1 = (B + 63) / 64 + 1;
    gemv_kernel<<<grid1, 256>>>((const float4*)x, (const float4*)Wpre, qw, B);

    // K2: one thread per row
    const int grid2 = (B + 255) / 256;
    circuit_kernel<<<grid2, 256>>>(bpre, Wpo, bpo, out, B);
}

// round 11
// speedup vs baseline: 1.3156x; 1.3156x over previous
#include <cuda_runtime.h>

#define PI_F 3.14159265358979323846f

// scratch: pre-activations pre[B][4], circuit unitary U[16][16] complex
__device__ float  g_pre[65536 * 4];
__device__ float2 g_U[256];          // g_U[j*16+k] = U[j][k] (amp j, column k)

// ---------------------------------------------------------------------------
// fold: butterfly step that merges two accumulators while halving lane span.
// ---------------------------------------------------------------------------
__device__ __forceinline__ float foldf(float a, float b, int m, int lane) {
    const float s = (lane & m) ? a : b;
    const float r = __shfl_xor_sync(0xffffffffu, s, m);
    return (((lane & m) ? b : a) + r);
}

__device__ __forceinline__ float dot4acc(const float4 a, const float4 b,
                                         float acc) {
    return fmaf(a.x, b.x, fmaf(a.y, b.y, fmaf(a.z, b.z,
           fmaf(a.w, b.w, acc))));
}

// ---------------------------------------------------------------------------
// K1: GEMV pre = x @ W_pre^T, W_pre register-resident (R5 proven version),
//     PLUS one extra block that builds the 16x16 circuit unitary U
//     (overlapped with the GEMV wave).
// ---------------------------------------------------------------------------
__global__ __launch_bounds__(256, 2) void gemv_kernel(
    const float4* __restrict__ x4,      // [B,128] float4
    const float4* __restrict__ Wpre4,   // [4,128] float4
    const float* __restrict__ q_weights,// [6,4,3]
    int B)
{
    const int tid  = threadIdx.x;
    const int lane = tid & 31;

    if (blockIdx.x == gridDim.x - 1) {
        // ================= U-builder block =================
        __shared__ float4 g_sh[24][2];     // gate coefficients
        __shared__ float2 S[16][16];       // [column][amplitude]
        __shared__ float2 T[16][16];

        if (tid < 24) {
            const float phi = q_weights[tid * 3 + 0];
            const float th  = q_weights[tid * 3 + 1];
            const float om  = q_weights[tid * 3 + 2];
            float c, s, cp, sp, cm, sm;
            sincosf(0.5f * th, &s, &c);
            sincosf(0.5f * (phi + om), &sp, &cp);
            sincosf(0.5f * (phi - om), &sm, &cm);
            g_sh[tid][0] = make_float4(cp * c, -sp * c, -cm * s, -sm * s);
            g_sh[tid][1] = make_float4(cm * s, -sm * s,  cp * c,  sp * c);
        }
        if (tid < 128) {
            const int c = tid >> 3;
            const int m = tid & 7;
            S[c][m]     = make_float2((m == c)     ? 1.f : 0.f, 0.f);
            S[c][m + 8] = make_float2((m + 8 == c) ? 1.f : 0.f, 0.f);
        }
        __syncthreads();

        if (tid < 128) {
            const int c = tid >> 3;
            const int m = tid & 7;
#pragma unroll 1
            for (int l = 0; l < 6; ++l) {
#pragma unroll
                for (int w = 0; w < 4; ++w) {
                    const int ST = 8 >> w;
                    const int i0 = ((m & ~(ST - 1)) << 1) | (m & (ST - 1));
                    const int i1 = i0 + ST;
                    const float4 g0 = g_sh[l * 4 + w][0];
                    const float4 g1 = g_sh[l * 4 + w][1];
                    const float2 a = S[c][i0];
                    const float2 b = S[c][i1];
                    S[c][i0] = make_float2(
                        g0.x * a.x - g0.y * a.y + g0.z * b.x - g0.w * b.y,
                        g0.x * a.y + g0.y * a.x + g0.z * b.y + g0.w * b.x);
                    S[c][i1] = make_float2(
                        g1.x * a.x - g1.y * a.y + g1.z * b.x - g1.w * b.y,
                        g1.x * a.y + g1.y * a.x + g1.z * b.y + g1.w * b.x);
                    __syncthreads();
                }
                const int R = l % 3 + 1;
#pragma unroll
                for (int half = 0; half < 2; ++half) {
                    const int i = m + half * 8;
                    int j = i;
#pragma unroll
                    for (int w = 0; w < 4; ++w)
                        if (j & (8 >> w)) j ^= (8 >> ((w + R) & 3));
                    T[c][j] = S[c][i];
                }
                __syncthreads();
                S[c][m]     = T[c][m];
                S[c][m + 8] = T[c][m + 8];
                __syncthreads();
            }
            g_U[m * 16 + c]       = S[c][m];
            g_U[(m + 8) * 16 + c] = S[c][m + 8];
        }
        return;
    }

    // ================= GEMV blocks (register-resident W) =================
    float4 wv[4][4];
#pragma unroll
    for (int it = 0; it < 4; ++it)
#pragma unroll
        for (int q = 0; q < 4; ++q)
            wv[it][q] = Wpre4[q * 128 + it * 32 + lane];

    const int gwarp   = (blockIdx.x * 256 + tid) >> 5;
    const int rowBase = gwarp * 8;

#pragma unroll 1
    for (int pi = 0; pi < 4; ++pi) {
        int r0 = rowBase + pi * 2;
        int r1 = r0 + 1;
        if (r0 >= B) r0 = B - 1;
        if (r1 >= B) r1 = B - 1;

        float4 xv0[4], xv1[4];
#pragma unroll
        for (int it = 0; it < 4; ++it)
            xv0[it] = x4[(long)r0 * 128 + it * 32 + lane];
#pragma unroll
        for (int it = 0; it < 4; ++it)
            xv1[it] = x4[(long)r1 * 128 + it * 32 + lane];

        float a0 = 0.f, a1 = 0.f, a2 = 0.f, a3 = 0.f;
        float b0 = 0.f, b1 = 0.f, b2 = 0.f, b3 = 0.f;
#pragma unroll
        for (int it = 0; it < 4; ++it) {
            a0 = dot4acc(xv0[it], wv[it][0], a0);
            a1 = dot4acc(xv0[it], wv[it][1], a1);
            a2 = dot4acc(xv0[it], wv[it][2], a2);
            a3 = dot4acc(xv0[it], wv[it][3], a3);
            b0 = dot4acc(xv1[it], wv[it][0], b0);
            b1 = dot4acc(xv1[it], wv[it][1], b1);
            b2 = dot4acc(xv1[it], wv[it][2], b2);
            b3 = dot4acc(xv1[it], wv[it][3], b3);
        }

        // packed reduction: 9 shuffles, lane bit4 = row, bits[3:2] = qubit.
        const float t0 = foldf(a0, b0, 16, lane);
        const float t1 = foldf(a1, b1, 16, lane);
        const float t2 = foldf(a2, b2, 16, lane);
        const float t3 = foldf(a3, b3, 16, lane);
        const float u0 = foldf(t0, t2, 8, lane);
        const float u1 = foldf(t1, t3, 8, lane);
        float v = foldf(u0, u1, 4, lane);
        v += __shfl_xor_sync(0xffffffffu, v, 2);
        v += __shfl_xor_sync(0xffffffffu, v, 1);

        if ((lane & 3) == 0) {
            const int rsel = lane >> 4;
            const int q = (lane >> 2) & 3;
            g_pre[(long)(rsel ? r1 : r0) * 4 + q] = v;
        }
    }
}

// ---------------------------------------------------------------------------
// K2: y = U * s0, TWO threads per row (each handles 8 of the 16 U-rows),
// lane-pair shuffle combine, each half writes 5 of the 10 outputs.
// ---------------------------------------------------------------------------
__global__ __launch_bounds__(256) void circuit_kernel(
    const float* __restrict__ b_pre,    // [4]
    const float* __restrict__ W_post,   // [10,4]
    const float* __restrict__ b_post,   // [10]
    float* __restrict__ out,            // [B,10]
    int B)
{
    __shared__ float2 Us[256];          // U[j][k], row-major
    __shared__ float  wpost_sh[40];
    __shared__ float  bpost_sh[10];

    const int tid = threadIdx.x;
    if (tid < 128)
        reinterpret_cast<float4*>(Us)[tid] =
            reinterpret_cast<const float4*>(g_U)[tid];
    else if (tid < 168)      wpost_sh[tid - 128] = W_post[tid - 128];
    else if (tid < 178)      bpost_sh[tid - 168] = b_post[tid - 168];
    __syncthreads();

    long row = (long)blockIdx.x * 128 + (tid >> 1);
    const int half = tid & 1;
    const bool valid = (row < B);
    if (row >= B) row = B - 1;

    const float4 p = *reinterpret_cast<const float4*>(g_pre + row * 4);

    float cw[4], sw[4];
    {
        float ang;
        ang = tanhf(p.x + __ldg(b_pre + 0)) * PI_F;
        __sincosf(0.5f * ang, &sw[0], &cw[0]);
        ang = tanhf(p.y + __ldg(b_pre + 1)) * PI_F;
        __sincosf(0.5f * ang, &sw[1], &cw[1]);
        ang = tanhf(p.z + __ldg(b_pre + 2)) * PI_F;
        __sincosf(0.5f * ang, &sw[2], &cw[2]);
        ang = tanhf(p.w + __ldg(b_pre + 3)) * PI_F;
        __sincosf(0.5f * ang, &sw[3], &cw[3]);
    }

    // real product state after the RY layer (full s0 needed by both halves)
    float s0[16];
#pragma unroll
    for (int i = 0; i < 16; ++i)
        s0[i] = ((i & 8) ? sw[0] : cw[0]) * ((i & 4) ? sw[1] : cw[1]) *
                ((i & 2) ? sw[2] : cw[2]) * ((i & 1) ? sw[3] : cw[3]);

    // this half's 8 rows of U
    float e0 = 0.f, e1 = 0.f, e2 = 0.f, e3 = 0.f;
    const int jBase = half * 8;
#pragma unroll
    for (int jj = 0; jj < 8; ++jj) {
        const int j = jBase + jj;
        const float4* Uj = reinterpret_cast<const float4*>(&Us[j * 16]);
        float yr = 0.f, yi = 0.f;
#pragma unroll
        for (int kk = 0; kk < 8; ++kk) {
            const float4 v = Uj[kk];            // (re_k, im_k, re_k+1, im_k+1)
            const float sa = s0[2 * kk];
            const float sb = s0[2 * kk + 1];
            yr = fmaf(v.x, sa, fmaf(v.z, sb, yr));
            yi = fmaf(v.y, sa, fmaf(v.w, sb, yi));
        }
        const float pr = fmaf(yr, yr, yi * yi);
        e0 += (j & 8) ? -pr : pr;
        e1 += (j & 4) ? -pr : pr;
        e2 += (j & 2) ? -pr : pr;
        e3 += (j & 1) ? -pr : pr;
    }

    // combine lane pair (both halves end with full expectations)
    e0 += __shfl_xor_sync(0xffffffffu, e0, 1);
    e1 += __shfl_xor_sync(0xffffffffu, e1, 1);
    e2 += __shfl_xor_sync(0xffffffffu, e2, 1);
    e3 += __shfl_xor_sync(0xffffffffu, e3, 1);

    if (!valid) return;

    // each half writes 5 of the 10 outputs
    const int cBase = half * 5;
    float* orow = out + row * 10;
#pragma unroll
    for (int cc = 0; cc < 5; ++cc) {
        const int c = cBase + cc;
        orow[c] = bpost_sh[c]
                + e0 * wpost_sh[c * 4 + 0] + e1 * wpost_sh[c * 4 + 1]
                + e2 * wpost_sh[c * 4 + 2] + e3 * wpost_sh[c * 4 + 3];
    }
}

extern "C" void kernel_launch(void* const* d_in, const int* in_sizes, int n_in,
                              void* d_out, int out_size) {
    const float* x    = (const float*)d_in[0];
    const float* Wpre = (const float*)d_in[1];
    const float* bpre = (const float*)d_in[2];
    const float* qw   = (const float*)d_in[3];
    const float* Wpo  = (const float*)d_in[4];
    const float* bpo  = (const float*)d_in[5];
    float* out = (float*)d_out;

    const int B = in_sizes[0] / 512;

    // K1: 64 rows per block + 1 extra block that builds U (overlapped)
    const int grid1 = (B + 63) / 64 + 1;
    gemv_kernel<<<grid1, 256>>>((const float4*)x, (const float4*)Wpre, qw, B);

    // K2: two threads per row -> 128 rows per 256-thread block
    const int grid2 = (B + 127) / 128;
    circuit_kernel<<<grid2, 256>>>(bpre, Wpo, bpo, out, B);
}